// round 9
// baseline (speedup 1.0000x reference)
#include <cuda_runtime.h>
#include <math.h>

#define BB   2
#define HH   96
#define WW   96
#define PIX  (HH*WW)        // 9216
#define CINX 2048
#define CIX  512
#define CQKX 64
#define NCL  19

// ---------------- scratch (static device globals; no allocation) ------------
__device__ float g_A  [BB*CIX*PIX];      // 37.75 MB
__device__ float g_Bf [BB*CIX*PIX];
__device__ float g_V  [BB*CIX*PIX];
__device__ float g_Q  [BB*CQKX*PIX];
__device__ float g_K  [BB*CQKX*PIX];
__device__ float g_Att[BB*PIX*192];

// ---------------- 3x3 conv, CO=512 fixed, tiled implicit GEMM ---------------
// tile: 128 co x (8 rows x 16 cols). 256 threads, micro 8co x 8rows x 1col.
// flags: 1 = accumulate into out, 2 = apply scale/bias, 4 = relu
__global__ void __launch_bounds__(256, 2)
conv3x3_kernel(const float* __restrict__ in, const float* __restrict__ wgt,
               const float* __restrict__ scale, const float* __restrict__ bias,
               float* __restrict__ out, int Cin, int WCin, int coff, int flags)
{
    const int tile_w = blockIdx.x * 16;
    const int tile_h = blockIdx.y * 8;
    const int b      = blockIdx.z >> 2;         // CO/128 = 4
    const int co0    = (blockIdx.z & 3) * 128;

    __shared__ float sIn[8][10][18];            // 1440 f
    __shared__ float sW[128][73];               // padded (72 used)

    const int tid = threadIdx.x;
    const int tx  = tid & 15;                   // output column within tile
    const int ty  = tid >> 4;                   // co group (8 channels)

    float acc[8][8];
#pragma unroll
    for (int i = 0; i < 8; ++i)
#pragma unroll
        for (int r = 0; r < 8; ++r) acc[i][r] = 0.f;

    const float* inb = in + (size_t)b * Cin * PIX;

    for (int ck0 = 0; ck0 < Cin; ck0 += 8) {
        __syncthreads();
        // input patch: 8 cin x 10 rows x 18 cols (zero-padded halo)
        for (int idx = tid; idx < 8*180; idx += 256) {
            int c  = idx / 180, rem = idx % 180;
            int r  = rem / 18,  cc  = rem % 18;
            int gh = tile_h - 1 + r, gw = tile_w - 1 + cc;
            float vv = 0.f;
            if ((unsigned)gh < 96u && (unsigned)gw < 96u)
                vv = inb[(size_t)(ck0 + c) * PIX + gh * 96 + gw];
            sIn[c][r][cc] = vv;
        }
        // weights: 128 co x 8 cin x 9 taps (contiguous per co)
        const float* wp = wgt + ((size_t)co0 * WCin + coff + ck0) * 9;
        for (int idx = tid; idx < 128*72; idx += 256) {
            int i = idx / 72, rem = idx - i * 72;
            sW[i][rem] = wp[(size_t)i * WCin * 9 + rem];
        }
        __syncthreads();

#pragma unroll 2
        for (int j = 0; j < 8; ++j) {
#pragma unroll
            for (int ky = 0; ky < 3; ++ky) {
#pragma unroll
                for (int kx = 0; kx < 3; ++kx) {
                    float iv[8];
#pragma unroll
                    for (int r = 0; r < 8; ++r) iv[r] = sIn[j][r + ky][tx + kx];
#pragma unroll
                    for (int i = 0; i < 8; ++i) {
                        float wv = sW[ty*8 + i][j*9 + ky*3 + kx];
#pragma unroll
                        for (int r = 0; r < 8; ++r)
                            acc[i][r] = fmaf(wv, iv[r], acc[i][r]);
                    }
                }
            }
        }
    }

#pragma unroll
    for (int i = 0; i < 8; ++i) {
        int co = co0 + ty*8 + i;
        float s = 1.f, bs = 0.f;
        if (flags & 2) { s = scale[co]; bs = bias[co]; }
#pragma unroll
        for (int r = 0; r < 8; ++r) {
            size_t oi = (((size_t)b*512 + co)*96 + tile_h + r)*96 + tile_w + tx;
            float vv = acc[i][r];
            if (flags & 1) vv += out[oi];
            vv = vv * s + bs;
            if (flags & 4) vv = fmaxf(vv, 0.f);
            out[oi] = vv;
        }
    }
}

// ---------------- 1x1 projection: out[b,o,p] = sum_c W[o,c] in[b,c,p] -------
__global__ void __launch_bounds__(256)
pw_kernel(const float* __restrict__ in, const float* __restrict__ wgt,
          float* __restrict__ out, int Cin, int CO)
{
    const int px0 = blockIdx.x * 128;
    const int o0  = blockIdx.y * 64;
    const int b   = blockIdx.z;
    __shared__ float sIn[16][128];
    __shared__ float sW[64][17];
    const int tid = threadIdx.x, tx = tid & 15, ty = tid >> 4;
    float acc[4][8];
#pragma unroll
    for (int i = 0; i < 4; ++i)
#pragma unroll
        for (int r = 0; r < 8; ++r) acc[i][r] = 0.f;

    const float* inb = in + (size_t)b * Cin * PIX;
    for (int c0 = 0; c0 < Cin; c0 += 16) {
        __syncthreads();
#pragma unroll
        for (int k = 0; k < 8; ++k) {
            int idx = tid + k*256;
            sIn[idx >> 7][idx & 127] =
                inb[(size_t)(c0 + (idx >> 7)) * PIX + px0 + (idx & 127)];
        }
#pragma unroll
        for (int k = 0; k < 4; ++k) {
            int idx = tid + k*256;
            sW[idx >> 4][idx & 15] =
                wgt[(size_t)(o0 + (idx >> 4)) * Cin + c0 + (idx & 15)];
        }
        __syncthreads();
#pragma unroll
        for (int j = 0; j < 16; ++j) {
            float iv[8];
#pragma unroll
            for (int r = 0; r < 8; ++r) iv[r] = sIn[j][tx + 16*r];
#pragma unroll
            for (int i = 0; i < 4; ++i) {
                float wv = sW[ty*4 + i][j];
#pragma unroll
                for (int r = 0; r < 8; ++r)
                    acc[i][r] = fmaf(wv, iv[r], acc[i][r]);
            }
        }
    }
#pragma unroll
    for (int i = 0; i < 4; ++i)
#pragma unroll
        for (int r = 0; r < 8; ++r)
            out[((size_t)b*CO + o0 + ty*4 + i)*PIX + px0 + tx + 16*r] = acc[i][r];
}

// ---------------- energies --------------------------------------------------
// eH[b,h,w,g] = sum_c q[b,c,h,w] k[b,c,g,w]   (mask g==h -> -inf), block=(w,b)
__global__ void __launch_bounds__(256)
energyH_kernel(const float* __restrict__ q, const float* __restrict__ k,
               float* __restrict__ att)
{
    const int w = blockIdx.x, b = blockIdx.y;
    __shared__ float sQ[32][96], sK[32][96];
    const int tid = threadIdx.x;
    float acc[36];
#pragma unroll
    for (int i = 0; i < 36; ++i) acc[i] = 0.f;

    for (int c0 = 0; c0 < CQKX; c0 += 32) {
        __syncthreads();
        for (int idx = tid; idx < 32*96; idx += 256) {
            int c = idx / 96, p = idx % 96;
            size_t off = (size_t)(b*CQKX + c0 + c) * PIX + p*96 + w;
            sQ[c][p] = q[off];
            sK[c][p] = k[off];
        }
        __syncthreads();
#pragma unroll
        for (int it = 0; it < 36; ++it) {
            int oi = it*256 + tid;
            int h = oi / 96, g = oi % 96;
            float s = acc[it];
#pragma unroll
            for (int c = 0; c < 32; ++c) s = fmaf(sQ[c][h], sK[c][g], s);
            acc[it] = s;
        }
    }
#pragma unroll
    for (int it = 0; it < 36; ++it) {
        int oi = it*256 + tid;
        int h = oi / 96, g = oi % 96;
        float vv = (g == h) ? __int_as_float(0xff800000u) : acc[it];
        att[((size_t)((b*96 + h)*96 + w))*192 + g] = vv;
    }
}

// eW[b,h,w,v] = sum_c q[b,c,h,w] k[b,c,h,v], block=(h,b)
__global__ void __launch_bounds__(256)
energyW_kernel(const float* __restrict__ q, const float* __restrict__ k,
               float* __restrict__ att)
{
    const int h = blockIdx.x, b = blockIdx.y;
    __shared__ float sQ[32][96], sK[32][96];
    const int tid = threadIdx.x;
    float acc[36];
#pragma unroll
    for (int i = 0; i < 36; ++i) acc[i] = 0.f;

    for (int c0 = 0; c0 < CQKX; c0 += 32) {
        __syncthreads();
        for (int idx = tid; idx < 32*96; idx += 256) {
            int c = idx / 96, p = idx % 96;
            size_t off = (size_t)(b*CQKX + c0 + c) * PIX + h*96 + p;
            sQ[c][p] = q[off];
            sK[c][p] = k[off];
        }
        __syncthreads();
#pragma unroll
        for (int it = 0; it < 36; ++it) {
            int oi = it*256 + tid;
            int wc = oi / 96, v2 = oi % 96;
            float s = acc[it];
#pragma unroll
            for (int c = 0; c < 32; ++c) s = fmaf(sQ[c][wc], sK[c][v2], s);
            acc[it] = s;
        }
    }
#pragma unroll
    for (int it = 0; it < 36; ++it) {
        int oi = it*256 + tid;
        int wc = oi / 96, v2 = oi % 96;
        att[((size_t)((b*96 + h)*96 + wc))*192 + 96 + v2] = acc[it];
    }
}

// ---------------- softmax over 192 ------------------------------------------
__global__ void softmax_kernel(float* __restrict__ att)
{
    const int t = threadIdx.x;                   // 192 threads
    const size_t base = (size_t)blockIdx.x * 192;
    float v = att[base + t];
    __shared__ float red[6];

    float m = v;
#pragma unroll
    for (int o = 16; o; o >>= 1) m = fmaxf(m, __shfl_xor_sync(0xffffffffu, m, o));
    if ((t & 31) == 0) red[t >> 5] = m;
    __syncthreads();
    m = fmaxf(fmaxf(fmaxf(red[0], red[1]), fmaxf(red[2], red[3])),
              fmaxf(red[4], red[5]));

    float e = expf(v - m);
    float s = e;
#pragma unroll
    for (int o = 16; o; o >>= 1) s += __shfl_xor_sync(0xffffffffu, s, o);
    __syncthreads();
    if ((t & 31) == 0) red[t >> 5] = s;
    __syncthreads();
    s = red[0] + red[1] + red[2] + red[3] + red[4] + red[5];
    att[base + t] = e / s;
}

// ---------------- aggregation -----------------------------------------------
// outH: dst[b,c,h,w] = feat + gamma * sum_g v[b,c,g,w] * aH[b,h,w,g], block=(w,b)
__global__ void __launch_bounds__(256)
aggH_kernel(const float* __restrict__ v, const float* __restrict__ att,
            const float* __restrict__ feat, const float* __restrict__ gp,
            float* __restrict__ dst)
{
    const int w = blockIdx.x, b = blockIdx.y;
    const int tid = threadIdx.x;
    __shared__ float sA[96][97];
    __shared__ float sV[16][97];
    const float gm = *gp;

    for (int idx = tid; idx < 96*96; idx += 256) {
        int h = idx / 96, g = idx % 96;
        sA[h][g] = att[((size_t)((b*96 + h)*96 + w))*192 + g];
    }
    const int clg = tid >> 5;      // 0..7 -> channels 2*clg, 2*clg+1
    const int hq  = tid & 31;      // h = hq + 32*r, r<3

    for (int c0 = 0; c0 < CIX; c0 += 16) {
        __syncthreads();
        for (int idx = tid; idx < 16*96; idx += 256) {
            int cl = idx / 96, g = idx % 96;
            sV[cl][g] = v[(size_t)(b*CIX + c0 + cl) * PIX + g*96 + w];
        }
        __syncthreads();
        float a0[3] = {0.f,0.f,0.f}, a1[3] = {0.f,0.f,0.f};
#pragma unroll 4
        for (int g = 0; g < 96; ++g) {
            float v0 = sV[clg*2][g], v1 = sV[clg*2+1][g];
#pragma unroll
            for (int r = 0; r < 3; ++r) {
                float a = sA[hq + 32*r][g];
                a0[r] = fmaf(v0, a, a0[r]);
                a1[r] = fmaf(v1, a, a1[r]);
            }
        }
#pragma unroll
        for (int r = 0; r < 3; ++r) {
            int h = hq + 32*r;
            size_t oi0 = ((size_t)(b*CIX + c0 + clg*2    )*96 + h)*96 + w;
            size_t oi1 = ((size_t)(b*CIX + c0 + clg*2 + 1)*96 + h)*96 + w;
            dst[oi0] = feat[oi0] + gm * a0[r];
            dst[oi1] = feat[oi1] + gm * a1[r];
        }
    }
}

// outW: dst[b,c,h,w] += gamma * sum_v v[b,c,h,v] * aW[b,h,w,v], block=(h,b)
__global__ void __launch_bounds__(256)
aggW_kernel(const float* __restrict__ v, const float* __restrict__ att,
            const float* __restrict__ gp, float* __restrict__ dst)
{
    const int h = blockIdx.x, b = blockIdx.y;
    const int tid = threadIdx.x;
    __shared__ float sA[96][97];
    __shared__ float sV[16][97];
    const float gm = *gp;

    for (int idx = tid; idx < 96*96; idx += 256) {
        int wc = idx / 96, v2 = idx % 96;
        sA[wc][v2] = att[((size_t)((b*96 + h)*96 + wc))*192 + 96 + v2];
    }
    const int clg = tid >> 5;
    const int wq  = tid & 31;

    for (int c0 = 0; c0 < CIX; c0 += 16) {
        __syncthreads();
        for (int idx = tid; idx < 16*96; idx += 256) {
            int cl = idx / 96, v2 = idx % 96;
            sV[cl][v2] = v[(size_t)(b*CIX + c0 + cl) * PIX + h*96 + v2];
        }
        __syncthreads();
        float a0[3] = {0.f,0.f,0.f}, a1[3] = {0.f,0.f,0.f};
#pragma unroll 4
        for (int v2 = 0; v2 < 96; ++v2) {
            float v0 = sV[clg*2][v2], v1 = sV[clg*2+1][v2];
#pragma unroll
            for (int r = 0; r < 3; ++r) {
                float a = sA[wq + 32*r][v2];
                a0[r] = fmaf(v0, a, a0[r]);
                a1[r] = fmaf(v1, a, a1[r]);
            }
        }
#pragma unroll
        for (int r = 0; r < 3; ++r) {
            int wc = wq + 32*r;
            size_t oi0 = ((size_t)(b*CIX + c0 + clg*2    )*96 + h)*96 + wc;
            size_t oi1 = ((size_t)(b*CIX + c0 + clg*2 + 1)*96 + h)*96 + wc;
            dst[oi0] += gm * a0[r];
            dst[oi1] += gm * a1[r];
        }
    }
}

// ---------------- final 1x1 (19 classes) + bias ------------------------------
__global__ void __launch_bounds__(256)
final_kernel(const float* __restrict__ in, const float* __restrict__ ow,
             const float* __restrict__ ob, float* __restrict__ out)
{
    const int px0 = blockIdx.x * 256;
    const int b   = blockIdx.y;
    const int tid = threadIdx.x;
    __shared__ float sIn[32][256];
    __shared__ float sW[19][32];
    float acc[NCL];
#pragma unroll
    for (int o = 0; o < NCL; ++o) acc[o] = 0.f;

    for (int c0 = 0; c0 < CIX; c0 += 32) {
        __syncthreads();
#pragma unroll
        for (int k = 0; k < 32; ++k)
            sIn[k][tid] = in[(size_t)(b*CIX + c0 + k) * PIX + px0 + tid];
        for (int idx = tid; idx < NCL*32; idx += 256)
            sW[idx >> 5][idx & 31] = ow[(size_t)(idx >> 5) * CIX + c0 + (idx & 31)];
        __syncthreads();
#pragma unroll
        for (int j = 0; j < 32; ++j) {
            float xv = sIn[j][tid];
#pragma unroll
            for (int o = 0; o < NCL; ++o) acc[o] = fmaf(sW[o][j], xv, acc[o]);
        }
    }
#pragma unroll
    for (int o = 0; o < NCL; ++o)
        out[((size_t)(b*NCL + o)) * PIX + px0 + tid] = acc[o] + ob[o];
}

// ---------------- launcher ---------------------------------------------------
extern "C" void kernel_launch(void* const* d_in, const int* in_sizes, int n_in,
                              void* d_out, int out_size)
{
    const float* x       = (const float*)d_in[0];
    const float* conva_w = (const float*)d_in[1];
    const float* bn1_s   = (const float*)d_in[2];
    const float* bn1_b   = (const float*)d_in[3];
    const float* q_w     = (const float*)d_in[4];
    const float* k_w     = (const float*)d_in[5];
    const float* v_w     = (const float*)d_in[6];
    const float* gamma   = (const float*)d_in[7];
    const float* convb_w = (const float*)d_in[8];
    const float* bn2_s   = (const float*)d_in[9];
    const float* bn2_b   = (const float*)d_in[10];
    const float* bott_w  = (const float*)d_in[11];
    const float* bn3_s   = (const float*)d_in[12];
    const float* bn3_b   = (const float*)d_in[13];
    const float* out_w   = (const float*)d_in[14];
    const float* out_b   = (const float*)d_in[15];
    float* out = (float*)d_out;

    float *pA, *pB, *pV, *pQ, *pK, *pAtt;
    cudaGetSymbolAddress((void**)&pA,   g_A);
    cudaGetSymbolAddress((void**)&pB,   g_Bf);
    cudaGetSymbolAddress((void**)&pV,   g_V);
    cudaGetSymbolAddress((void**)&pQ,   g_Q);
    cudaGetSymbolAddress((void**)&pK,   g_K);
    cudaGetSymbolAddress((void**)&pAtt, g_Att);

    dim3 cgrid(6, 12, BB * (CIX/128));   // (6,12,8)

    // conva + bn1 + relu -> A
    conv3x3_kernel<<<cgrid, 256>>>(x, conva_w, bn1_s, bn1_b, pA,
                                   CINX, CINX, 0, 2|4);

    // 2 recurrences of criss-cross attention
    for (int r = 0; r < 2; ++r) {
        const float* feat = r ? pB : pA;
        float*       dst  = r ? pA : pB;
        pw_kernel<<<dim3(72, 1, BB), 256>>>(feat, q_w, pQ, CIX, CQKX);
        pw_kernel<<<dim3(72, 1, BB), 256>>>(feat, k_w, pK, CIX, CQKX);
        pw_kernel<<<dim3(72, 8, BB), 256>>>(feat, v_w, pV, CIX, CIX);
        energyH_kernel<<<dim3(96, BB), 256>>>(pQ, pK, pAtt);
        energyW_kernel<<<dim3(96, BB), 256>>>(pQ, pK, pAtt);
        softmax_kernel<<<BB*PIX, 192>>>(pAtt);
        aggH_kernel<<<dim3(96, BB), 256>>>(pV, pAtt, feat, gamma, dst);
        aggW_kernel<<<dim3(96, BB), 256>>>(pV, pAtt, gamma, dst);
    }

    // convb + bn2 + relu : A -> B
    conv3x3_kernel<<<cgrid, 256>>>(pA, convb_w, bn2_s, bn2_b, pB,
                                   CIX, CIX, 0, 2|4);

    // bottleneck conv over virtual concat [x (2048ch), B (512ch)] -> V, bn3
    conv3x3_kernel<<<cgrid, 256>>>(x,  bott_w, nullptr, nullptr, pV,
                                   CINX, CINX + CIX, 0, 0);
    conv3x3_kernel<<<cgrid, 256>>>(pB, bott_w, bn3_s, bn3_b, pV,
                                   CIX, CINX + CIX, CINX, 1|2);

    // final 1x1 -> d_out
    final_kernel<<<dim3(PIX/256, BB), 256>>>(pV, out_w, out_b, out);
}